// round 12
// baseline (speedup 1.0000x reference)
#include <cuda_runtime.h>
#include <cuda_fp16.h>
#include <cstdint>
#include <math.h>

#define BB   2
#define HH   64
#define WW   64
#define CC   256
#define NHE  8
#define HDIM 32
#define KWIN 7
#define NPIX (BB*HH*WW)   // 8192

// ---------------- scratch (no allocation allowed) ----------------
__device__ __align__(16) __half g_xn  [NPIX * CC];
__device__ float               g_qkv [NPIX * 3 * CC];
__device__ __align__(16) __half g_attn[NPIX * CC];
__device__ __align__(16) __half g_hn  [NPIX * CC];
__device__ __align__(16) __half g_h1  [NPIX * 4 * CC];
__device__ __align__(16) __half g_wh  [12 * CC * CC];   // fp16 weights: qkv|proj|fc1|fc2

// ======================= PTX helpers (sm_80-era only; target is plain sm_103) ===============
__device__ __forceinline__ uint32_t smem_u32(const void* p) {
    uint32_t a;
    asm("{ .reg .u64 t; cvta.to.shared.u64 t, %1; cvt.u32.u64 %0, t; }" : "=r"(a) : "l"(p));
    return a;
}

#define CP_ASYNC16(dst, src) \
    asm volatile("cp.async.cg.shared.global [%0], [%1], 16;" :: "r"(dst), "l"(src) : "memory")
#define CP_COMMIT()  asm volatile("cp.async.commit_group;" ::: "memory")
#define CP_WAIT(n)   asm volatile("cp.async.wait_group %0;" :: "n"(n) : "memory")

__device__ __forceinline__ void ldsm_x4(uint32_t* r, uint32_t addr) {
    asm volatile("ldmatrix.sync.aligned.m8n8.x4.shared.b16 {%0,%1,%2,%3}, [%4];"
                 : "=r"(r[0]), "=r"(r[1]), "=r"(r[2]), "=r"(r[3]) : "r"(addr));
}

__device__ __forceinline__ void mma_f16(float* c, const uint32_t* a, const uint32_t* b) {
    asm volatile("mma.sync.aligned.m16n8k16.row.col.f32.f16.f16.f32 "
                 "{%0,%1,%2,%3}, {%4,%5,%6,%7}, {%8,%9}, {%0,%1,%2,%3};"
                 : "+f"(c[0]), "+f"(c[1]), "+f"(c[2]), "+f"(c[3])
                 : "r"(a[0]), "r"(a[1]), "r"(a[2]), "r"(a[3]), "r"(b[0]), "r"(b[1]));
}

__device__ __forceinline__ uint32_t pack_h2(float x, float y) {
    __half2 h = __floats2half2_rn(x, y);
    return *(uint32_t*)&h;
}

// fp16 SMEM tile: rows x 32 halfs (64B data), padded to 80B pitch.
#define TPH      80
#define TILE_A_H (128 * TPH)                          // 10240 B

// ---------------- convert weights to fp16 (RN) ----------------
// concatenated float4 ranges: qkv 49152 | proj 16384 | fc1 65536 | fc2 65536
__global__ void round_weights(const float4* __restrict__ w0,
                              const float4* __restrict__ w1,
                              const float4* __restrict__ w2,
                              const float4* __restrict__ w3,
                              __half2* __restrict__ out) {
    int i = blockIdx.x * 256 + threadIdx.x;     // 0 .. 196607
    const float4* src;
    int off;
    if      (i <  49152) { src = w0; off = 0;      }
    else if (i <  65536) { src = w1; off = 49152;  }
    else if (i < 131072) { src = w2; off = 65536;  }
    else                 { src = w3; off = 131072; }
    float4 v = src[i - off];
    out[2 * i]     = __floats2half2_rn(v.x, v.y);
    out[2 * i + 1] = __floats2half2_rn(v.z, v.w);
}

// ============ fp16 m16n8k16 GEMM, 3-stage pipeline ============
// out[M,N] = A[M,K] * W[N,K]^T + bias (+res/+gelu).  Tile: 128 x BN (BN in {128, 64}).
// EPI: 0 = bias, 1 = bias + residual, 2 = bias + exact GELU
// OUTH: 0 = fp32 output, 1 = fp16 output
template <int EPI, int BN, int OUTH>
__global__ void __launch_bounds__(256, 2)
gemm_tc(const __half* __restrict__ A,
        const __half* __restrict__ Wm,
        const float* __restrict__ bias,
        const float* __restrict__ res,
        void* __restrict__ outv,
        int M, int N, int Kd) {
    constexpr int WN    = BN / 32;        // warps along N
    constexpr int WM    = 8 / WN;         // warps along M
    constexpr int MT    = 128 / (16 * WM);// m16 tiles per warp
    constexpr int STAGE = TILE_A_H + BN * TPH;

    extern __shared__ __align__(1024) char smem[];
    const uint32_t sb = smem_u32(smem);

    const int tid  = threadIdx.x;
    const int wid  = tid >> 5;
    const int lane = tid & 31;
    const int wm   = wid / WN;
    const int wn   = wid % WN;
    const int m0   = blockIdx.y * 128;
    const int n0   = blockIdx.x * BN;
    const int niters = Kd >> 5;           // K slabs of 32 halfs (64B)

    const int sub = lane >> 3;
    const int mr  = lane & 7;
    const uint32_t aoff = (uint32_t)((wm * (MT * 16) + (sub & 1) * 8 + mr) * TPH + (sub >> 1) * 16);
    const uint32_t boff = (uint32_t)(TILE_A_H + (wn * 32 + (sub >> 1) * 8 + mr) * TPH + (sub & 1) * 16);

    float acc[MT][4][4];
    #pragma unroll
    for (int i = 0; i < MT; i++)
        #pragma unroll
        for (int j = 0; j < 4; j++)
            #pragma unroll
            for (int k = 0; k < 4; k++) acc[i][j][k] = 0.0f;

    auto load_stage = [&](int it, int s) {
        const uint32_t base = sb + s * STAGE;
        #pragma unroll
        for (int idx = 0; idx < 2; idx++) {
            const int t = tid + idx * 256;        // 0..511 (128 rows x 4 chunks)
            const int row = t >> 2, c = t & 3;
            CP_ASYNC16(base + row * TPH + c * 16,
                       A + (size_t)(m0 + row) * Kd + it * 32 + c * 8);
        }
        #pragma unroll
        for (int idx = 0; idx < BN / 64; idx++) {
            const int t = tid + idx * 256;        // 0..BN*4-1
            const int row = t >> 2, c = t & 3;
            CP_ASYNC16(base + TILE_A_H + row * TPH + c * 16,
                       Wm + (size_t)(n0 + row) * Kd + it * 32 + c * 8);
        }
    };

    load_stage(0, 0); CP_COMMIT();
    load_stage(1, 1); CP_COMMIT();

    for (int it = 0; it < niters; it++) {
        const int s = it - (it / 3) * 3;
        CP_WAIT(1);                 // stage `it` resident
        __syncthreads();
        const int p = it + 2;
        if (p < niters) load_stage(p, p - (p / 3) * 3);
        CP_COMMIT();

        const uint32_t Ab = sb + s * STAGE;

        #pragma unroll
        for (int ks = 0; ks < 2; ks++) {          // two k16 steps per 32-half slab
            uint32_t af[MT][4];
            #pragma unroll
            for (int mt = 0; mt < MT; mt++)
                ldsm_x4(af[mt], Ab + aoff + mt * (16 * TPH) + ks * 32);
            uint32_t bf[8];
            #pragma unroll
            for (int pp = 0; pp < 2; pp++)
                ldsm_x4(&bf[pp * 4], Ab + boff + pp * (16 * TPH) + ks * 32);
            #pragma unroll
            for (int mt = 0; mt < MT; mt++)
                #pragma unroll
                for (int nt = 0; nt < 4; nt++)
                    mma_f16(acc[mt][nt], af[mt], &bf[(nt >> 1) * 4 + (nt & 1) * 2]);
        }
    }
    __syncthreads();

    float*  outf = (float*)outv;
    __half* outh = (__half*)outv;
    const int gid = lane >> 2;
    const int tig = lane & 3;
    #pragma unroll
    for (int nt = 0; nt < 4; nt++) {
        const int n = n0 + wn * 32 + nt * 8 + 2 * tig;
        const float2 bn = *(const float2*)(bias + n);
        #pragma unroll
        for (int mt = 0; mt < MT; mt++) {
            const int r0 = m0 + wm * (MT * 16) + mt * 16 + gid;
            const int r1 = r0 + 8;
            float v0 = acc[mt][nt][0] + bn.x;
            float v1 = acc[mt][nt][1] + bn.y;
            float v2 = acc[mt][nt][2] + bn.x;
            float v3 = acc[mt][nt][3] + bn.y;
            if (EPI == 1) {
                const float2 q0 = *(const float2*)(res + (size_t)r0 * N + n);
                const float2 q1 = *(const float2*)(res + (size_t)r1 * N + n);
                v0 += q0.x; v1 += q0.y; v2 += q1.x; v3 += q1.y;
            }
            if (EPI == 2) {
                v0 = 0.5f * v0 * (1.0f + erff(v0 * 0.70710678118654752f));
                v1 = 0.5f * v1 * (1.0f + erff(v1 * 0.70710678118654752f));
                v2 = 0.5f * v2 * (1.0f + erff(v2 * 0.70710678118654752f));
                v3 = 0.5f * v3 * (1.0f + erff(v3 * 0.70710678118654752f));
            }
            if (OUTH) {
                *(__half2*)(outh + (size_t)r0 * N + n) = __floats2half2_rn(v0, v1);
                *(__half2*)(outh + (size_t)r1 * N + n) = __floats2half2_rn(v2, v3);
            } else {
                *(float2*)(outf + (size_t)r0 * N + n) = make_float2(v0, v1);
                *(float2*)(outf + (size_t)r1 * N + n) = make_float2(v2, v3);
            }
        }
    }
}

// ---------------- LayerNorm (fp32 in, fp16 out: feeds a GEMM only) ----------------
__global__ void ln_kernel(const float* __restrict__ x,
                          const float* __restrict__ w,
                          const float* __restrict__ b,
                          __half* __restrict__ out) {
    int row = blockIdx.x;
    int t = threadIdx.x;
    float v = x[row * CC + t];
    __shared__ float s1[256];
    __shared__ float s2[256];
    s1[t] = v; s2[t] = v * v;
    __syncthreads();
    #pragma unroll
    for (int off = 128; off > 0; off >>= 1) {
        if (t < off) { s1[t] += s1[t + off]; s2[t] += s2[t + off]; }
        __syncthreads();
    }
    float m   = s1[0] * (1.0f / CC);
    float var = s2[0] * (1.0f / CC) - m * m;
    float r   = rsqrtf(var + 1e-5f);
    out[row * CC + t] = __float2half_rn((v - m) * r * w[t] + b[t]);
}

// ---------------- tiled neighborhood attention (fp16 SMEM halo, fp32 compute) ----------------
// 128 blocks (one full wave), 512 threads; block = (16x16 tile, head PAIR, batch).
// Lane pairs (tx, tx+16) split the 32 head channels; one shfl combines scores.
#define TS    16
#define HALO  22          // TS + 6
#define NHPIX (HALO*HALO) // 484
#define PPH   40          // halfs per halo pixel (32 data + 8 pad); 80B pitch
#define NATT_SMEM (2 * NHPIX * PPH * 2)   // 77440 B (K + V, fp16)

__global__ void __launch_bounds__(512)
natt_tile(const float* __restrict__ qkv, __half* __restrict__ out) {
    extern __shared__ __half hsm[];
    __half* ks = hsm;
    __half* vs = hsm + NHPIX * PPH;

    const int tile  = blockIdx.x;         // 0..15 (4x4 tiles)
    const int hpair = blockIdx.y;         // 0..3
    const int b     = blockIdx.z;
    const int ti0 = (tile >> 2) * TS;
    const int tj0 = (tile & 3) * TS;
    const int tid = threadIdx.x;

    const int lane = tid & 31;
    const int tx   = lane & 15;
    const int half = lane >> 4;           // channel half: 0 or 1
    const int ty   = tid >> 5;            // 0..15
    const int choff = half * 16;          // channel offset within head

    const int hbr = ti0 - 3;
    const int hbc = tj0 - 3;
    const int i = ti0 + ty;
    const int j = tj0 + tx;
    const size_t pix = (size_t)((b * HH + i) * WW + j);

    const int si = min(max(i - 3, 0), HH - KWIN);
    const int sj = min(max(j - 3, 0), WW - KWIN);
    const int lr0 = si - hbr;
    const int lc0 = sj - hbc;

    #pragma unroll
    for (int hp = 0; hp < 2; hp++) {
        const int head  = hpair * 2 + hp;
        const int hbase = head * HDIM;

        // ---- stage K and V halos (fp32 global -> fp16 smem) ----
        // chunk = 8 channels (2 float4 loads -> 1 uint4 store of 8 halfs)
        for (int idx = tid; idx < NHPIX * 4; idx += 512) {
            const int p  = idx >> 2;
            const int c  = idx & 3;            // 8-channel chunk
            const int hr = p / HALO;
            const int hc = p - hr * HALO;
            const int gr = min(max(hbr + hr, 0), HH - 1);
            const int gc = min(max(hbc + hc, 0), WW - 1);
            const size_t gpix = (size_t)((b * HH + gr) * WW + gc);
            const float* base = qkv + gpix * 768 + hbase + c * 8;
            // K
            {
                float4 a = *(const float4*)(base + 256);
                float4 d = *(const float4*)(base + 260);
                uint4 pk;
                pk.x = pack_h2(a.x, a.y); pk.y = pack_h2(a.z, a.w);
                pk.z = pack_h2(d.x, d.y); pk.w = pack_h2(d.z, d.w);
                *(uint4*)(ks + p * PPH + c * 8) = pk;
            }
            // V
            {
                float4 a = *(const float4*)(base + 512);
                float4 d = *(const float4*)(base + 516);
                uint4 pv;
                pv.x = pack_h2(a.x, a.y); pv.y = pack_h2(a.z, a.w);
                pv.z = pack_h2(d.x, d.y); pv.w = pack_h2(d.z, d.w);
                *(uint4*)(vs + p * PPH + c * 8) = pv;
            }
        }

        // ---- q (this thread's 16 channels), pre-scaled; overlaps staging ----
        float qf[16];
        {
            const float4* qp = (const float4*)(qkv + pix * 768 + hbase + choff);
            #pragma unroll
            for (int c = 0; c < 4; c++) {
                float4 v = qp[c];
                qf[4*c+0] = v.x * 0.17677669529663687f;
                qf[4*c+1] = v.y * 0.17677669529663687f;
                qf[4*c+2] = v.z * 0.17677669529663687f;
                qf[4*c+3] = v.w * 0.17677669529663687f;
            }
        }
        __syncthreads();

        // ---- QK: 49 half-scores (fp16 K, fp32 accum), combine via 1 shuffle ----
        float sc[49];
        #pragma unroll
        for (int dr = 0; dr < 7; dr++) {
            const __half* rowp = ks + (lr0 + dr) * (HALO * PPH) + lc0 * PPH + choff;
            #pragma unroll
            for (int dc = 0; dc < 7; dc++) {
                const uint4 r0 = *(const uint4*)(rowp + dc * PPH);
                const uint4 r1 = *(const uint4*)(rowp + dc * PPH + 8);
                float d0 = 0.f, d1 = 0.f;
                const uint32_t rw[8] = {r0.x, r0.y, r0.z, r0.w, r1.x, r1.y, r1.z, r1.w};
                #pragma unroll
                for (int c = 0; c < 8; c++) {
                    float2 f = __half22float2(*(const __half2*)&rw[c]);
                    d0 = fmaf(qf[2*c],   f.x, d0);
                    d1 = fmaf(qf[2*c+1], f.y, d1);
                }
                sc[dr * 7 + dc] = d0 + d1;
            }
        }
        #pragma unroll
        for (int n = 0; n < 49; n++)
            sc[n] += __shfl_xor_sync(0xFFFFFFFFu, sc[n], 16);

        // ---- softmax (in-thread; redundant across the lane pair) ----
        float m = sc[0];
        #pragma unroll
        for (int n = 1; n < 49; n++) m = fmaxf(m, sc[n]);
        float den = 0.f;
        #pragma unroll
        for (int n = 0; n < 49; n++) { sc[n] = __expf(sc[n] - m); den += sc[n]; }
        const float inv = 1.0f / den;

        // ---- AV over this thread's 16 channels (fp16 V, fp32 accum) ----
        float acc[16];
        #pragma unroll
        for (int c = 0; c < 16; c++) acc[c] = 0.f;
        #pragma unroll
        for (int dr = 0; dr < 7; dr++) {
            const __half* rowp = vs + (lr0 + dr) * (HALO * PPH) + lc0 * PPH + choff;
            #pragma unroll
            for (int dc = 0; dc < 7; dc++) {
                const float w = sc[dr * 7 + dc];
                const uint4 r0 = *(const uint4*)(rowp + dc * PPH);
                const uint4 r1 = *(const uint4*)(rowp + dc * PPH + 8);
                const uint32_t rw[8] = {r0.x, r0.y, r0.z, r0.w, r1.x, r1.y, r1.z, r1.w};
                #pragma unroll
                for (int c = 0; c < 8; c++) {
                    float2 f = __half22float2(*(const __half2*)&rw[c]);
                    acc[2*c]   = fmaf(w, f.x, acc[2*c]);
                    acc[2*c+1] = fmaf(w, f.y, acc[2*c+1]);
                }
            }
        }

        __half2* op = (__half2*)(out + pix * CC + hbase + choff);
        #pragma unroll
        for (int c = 0; c < 8; c++)
            op[c] = __floats2half2_rn(acc[2*c] * inv, acc[2*c+1] * inv);

        if (hp == 0) __syncthreads();   // all reads done before restaging
    }
}

// ---------------- host launcher ----------------
extern "C" void kernel_launch(void* const* d_in, const int* in_sizes, int n_in,
                              void* d_out, int out_size) {
    const float* x      = (const float*)d_in[0];
    const float* ln1_w  = (const float*)d_in[1];
    const float* ln1_b  = (const float*)d_in[2];
    const float* qkv_w  = (const float*)d_in[3];
    const float* qkv_b  = (const float*)d_in[4];
    const float* proj_w = (const float*)d_in[5];
    const float* proj_b = (const float*)d_in[6];
    const float* ln2_w  = (const float*)d_in[7];
    const float* ln2_b  = (const float*)d_in[8];
    const float* fc1_w  = (const float*)d_in[9];
    const float* fc1_b  = (const float*)d_in[10];
    const float* fc2_w  = (const float*)d_in[11];
    const float* fc2_b  = (const float*)d_in[12];
    float* out = (float*)d_out;

    __half *xn, *attn, *hn, *h1, *wh;
    float *qkv;
    cudaGetSymbolAddress((void**)&xn,   g_xn);
    cudaGetSymbolAddress((void**)&qkv,  g_qkv);
    cudaGetSymbolAddress((void**)&attn, g_attn);
    cudaGetSymbolAddress((void**)&hn,   g_hn);
    cudaGetSymbolAddress((void**)&h1,   g_h1);
    cudaGetSymbolAddress((void**)&wh,   g_wh);

    const __half* wh_qkv  = wh;                      // 196608 halfs
    const __half* wh_proj = wh + 196608;             // 65536
    const __half* wh_fc1  = wh + 262144;             // 262144
    const __half* wh_fc2  = wh + 524288;             // 262144

    constexpr int SM128 = 3 * (TILE_A_H + 128 * TPH);  // 61440
    constexpr int SM64  = 3 * (TILE_A_H + 64  * TPH);  // 46080

    cudaFuncSetAttribute((const void*)gemm_tc<0,128,0>, cudaFuncAttributeMaxDynamicSharedMemorySize, SM128);
    cudaFuncSetAttribute((const void*)gemm_tc<2,128,1>, cudaFuncAttributeMaxDynamicSharedMemorySize, SM128);
    cudaFuncSetAttribute((const void*)gemm_tc<1,64,0>,  cudaFuncAttributeMaxDynamicSharedMemorySize, SM64);
    cudaFuncSetAttribute((const void*)natt_tile,        cudaFuncAttributeMaxDynamicSharedMemorySize, NATT_SMEM);

    // 0. convert all weights to fp16 (RN)
    round_weights<<<768, 256>>>((const float4*)qkv_w, (const float4*)proj_w,
                                (const float4*)fc1_w, (const float4*)fc2_w,
                                (__half2*)wh);

    // 1. LN1 -> fp16
    ln_kernel<<<NPIX, 256>>>(x, ln1_w, ln1_b, xn);

    // 2. QKV GEMM: [8192,256] x [768,256]^T -> fp32 (attention reads fp32)
    gemm_tc<0,128,0><<<dim3(768 / 128, NPIX / 128), 256, SM128>>>(
        xn, wh_qkv, qkv_b, nullptr, qkv, NPIX, 768, CC);

    // 3. tiled neighborhood attention (fp16 halo) -> fp16
    natt_tile<<<dim3(16, NHE / 2, BB), 512, NATT_SMEM>>>(qkv, attn);

    // 4. proj GEMM + bias + residual(x) -> fp32 d_out   (BN=64: 256 blocks)
    gemm_tc<1,64,0><<<dim3(CC / 64, NPIX / 128), 256, SM64>>>(
        attn, wh_proj, proj_b, x, out, NPIX, CC, CC);

    // 5. LN2 -> fp16
    ln_kernel<<<NPIX, 256>>>(out, ln2_w, ln2_b, hn);

    // 6. fc1 GEMM + exact GELU -> fp16
    gemm_tc<2,128,1><<<dim3(1024 / 128, NPIX / 128), 256, SM128>>>(
        hn, wh_fc1, fc1_b, nullptr, h1, NPIX, 1024, CC);

    // 7. fc2 GEMM + bias + residual(d_out) -> fp32 d_out   (BN=64: 256 blocks)
    gemm_tc<1,64,0><<<dim3(CC / 64, NPIX / 128), 256, SM64>>>(
        h1, wh_fc2, fc2_b, out, out, NPIX, CC, 1024);
}

// round 13
// speedup vs baseline: 1.0492x; 1.0492x over previous
#include <cuda_runtime.h>
#include <cuda_fp16.h>
#include <cstdint>
#include <math.h>

#define BB   2
#define HH   64
#define WW   64
#define CC   256
#define NHE  8
#define HDIM 32
#define KWIN 7
#define NPIX (BB*HH*WW)   // 8192

// ---------------- scratch (no allocation allowed) ----------------
__device__ __align__(16) __half g_xn  [NPIX * CC];
__device__ float               g_qkv [NPIX * 3 * CC];
__device__ __align__(16) __half g_attn[NPIX * CC];
__device__ __align__(16) __half g_hn  [NPIX * CC];
__device__ __align__(16) __half g_h1  [NPIX * 4 * CC];
__device__ __align__(16) __half g_wh  [12 * CC * CC];   // fp16 weights: qkv|proj|fc1|fc2

// ======================= PTX helpers (sm_80-era only; target is plain sm_103) ===============
__device__ __forceinline__ uint32_t smem_u32(const void* p) {
    uint32_t a;
    asm("{ .reg .u64 t; cvta.to.shared.u64 t, %1; cvt.u32.u64 %0, t; }" : "=r"(a) : "l"(p));
    return a;
}

#define CP_ASYNC16(dst, src) \
    asm volatile("cp.async.cg.shared.global [%0], [%1], 16;" :: "r"(dst), "l"(src) : "memory")
#define CP_COMMIT()  asm volatile("cp.async.commit_group;" ::: "memory")
#define CP_WAIT(n)   asm volatile("cp.async.wait_group %0;" :: "n"(n) : "memory")

__device__ __forceinline__ void ldsm_x4(uint32_t* r, uint32_t addr) {
    asm volatile("ldmatrix.sync.aligned.m8n8.x4.shared.b16 {%0,%1,%2,%3}, [%4];"
                 : "=r"(r[0]), "=r"(r[1]), "=r"(r[2]), "=r"(r[3]) : "r"(addr));
}

__device__ __forceinline__ void mma_f16(float* c, const uint32_t* a, const uint32_t* b) {
    asm volatile("mma.sync.aligned.m16n8k16.row.col.f32.f16.f16.f32 "
                 "{%0,%1,%2,%3}, {%4,%5,%6,%7}, {%8,%9}, {%0,%1,%2,%3};"
                 : "+f"(c[0]), "+f"(c[1]), "+f"(c[2]), "+f"(c[3])
                 : "r"(a[0]), "r"(a[1]), "r"(a[2]), "r"(a[3]), "r"(b[0]), "r"(b[1]));
}

__device__ __forceinline__ uint32_t pack_h2(float x, float y) {
    __half2 h = __floats2half2_rn(x, y);
    return *(uint32_t*)&h;
}

__device__ __forceinline__ float2 unpack_h2(uint32_t u) {
    return __half22float2(*(const __half2*)&u);
}

// fp16 SMEM tile: rows x 32 halfs (64B data), padded to 80B pitch.
#define TPH      80
#define TILE_A_H (128 * TPH)                          // 10240 B

// ---------------- convert weights to fp16 (RN) ----------------
// concatenated float4 ranges: qkv 49152 | proj 16384 | fc1 65536 | fc2 65536
__global__ void round_weights(const float4* __restrict__ w0,
                              const float4* __restrict__ w1,
                              const float4* __restrict__ w2,
                              const float4* __restrict__ w3,
                              __half2* __restrict__ out) {
    int i = blockIdx.x * 256 + threadIdx.x;     // 0 .. 196607
    const float4* src;
    int off;
    if      (i <  49152) { src = w0; off = 0;      }
    else if (i <  65536) { src = w1; off = 49152;  }
    else if (i < 131072) { src = w2; off = 65536;  }
    else                 { src = w3; off = 131072; }
    float4 v = src[i - off];
    out[2 * i]     = __floats2half2_rn(v.x, v.y);
    out[2 * i + 1] = __floats2half2_rn(v.z, v.w);
}

// ============ fp16 m16n8k16 GEMM, 3-stage pipeline ============
// out[M,N] = A[M,K] * W[N,K]^T + bias (+res/+gelu).  Tile: 128 x BN (BN in {128, 64}).
// EPI: 0 = bias, 1 = bias + residual, 2 = bias + exact GELU
// OUTH: 0 = fp32 output, 1 = fp16 output
template <int EPI, int BN, int OUTH>
__global__ void __launch_bounds__(256, 2)
gemm_tc(const __half* __restrict__ A,
        const __half* __restrict__ Wm,
        const float* __restrict__ bias,
        const float* __restrict__ res,
        void* __restrict__ outv,
        int M, int N, int Kd) {
    constexpr int WN    = BN / 32;        // warps along N
    constexpr int WM    = 8 / WN;         // warps along M
    constexpr int MT    = 128 / (16 * WM);// m16 tiles per warp
    constexpr int STAGE = TILE_A_H + BN * TPH;

    extern __shared__ __align__(1024) char smem[];
    const uint32_t sb = smem_u32(smem);

    const int tid  = threadIdx.x;
    const int wid  = tid >> 5;
    const int lane = tid & 31;
    const int wm   = wid / WN;
    const int wn   = wid % WN;
    const int m0   = blockIdx.y * 128;
    const int n0   = blockIdx.x * BN;
    const int niters = Kd >> 5;           // K slabs of 32 halfs (64B)

    const int sub = lane >> 3;
    const int mr  = lane & 7;
    const uint32_t aoff = (uint32_t)((wm * (MT * 16) + (sub & 1) * 8 + mr) * TPH + (sub >> 1) * 16);
    const uint32_t boff = (uint32_t)(TILE_A_H + (wn * 32 + (sub >> 1) * 8 + mr) * TPH + (sub & 1) * 16);

    float acc[MT][4][4];
    #pragma unroll
    for (int i = 0; i < MT; i++)
        #pragma unroll
        for (int j = 0; j < 4; j++)
            #pragma unroll
            for (int k = 0; k < 4; k++) acc[i][j][k] = 0.0f;

    auto load_stage = [&](int it, int s) {
        const uint32_t base = sb + s * STAGE;
        #pragma unroll
        for (int idx = 0; idx < 2; idx++) {
            const int t = tid + idx * 256;        // 0..511 (128 rows x 4 chunks)
            const int row = t >> 2, c = t & 3;
            CP_ASYNC16(base + row * TPH + c * 16,
                       A + (size_t)(m0 + row) * Kd + it * 32 + c * 8);
        }
        #pragma unroll
        for (int idx = 0; idx < BN / 64; idx++) {
            const int t = tid + idx * 256;        // 0..BN*4-1
            const int row = t >> 2, c = t & 3;
            CP_ASYNC16(base + TILE_A_H + row * TPH + c * 16,
                       Wm + (size_t)(n0 + row) * Kd + it * 32 + c * 8);
        }
    };

    load_stage(0, 0); CP_COMMIT();
    load_stage(1, 1); CP_COMMIT();

    for (int it = 0; it < niters; it++) {
        const int s = it - (it / 3) * 3;
        CP_WAIT(1);                 // stage `it` resident
        __syncthreads();
        const int p = it + 2;
        if (p < niters) load_stage(p, p - (p / 3) * 3);
        CP_COMMIT();

        const uint32_t Ab = sb + s * STAGE;

        #pragma unroll
        for (int ks = 0; ks < 2; ks++) {          // two k16 steps per 32-half slab
            uint32_t af[MT][4];
            #pragma unroll
            for (int mt = 0; mt < MT; mt++)
                ldsm_x4(af[mt], Ab + aoff + mt * (16 * TPH) + ks * 32);
            uint32_t bf[8];
            #pragma unroll
            for (int pp = 0; pp < 2; pp++)
                ldsm_x4(&bf[pp * 4], Ab + boff + pp * (16 * TPH) + ks * 32);
            #pragma unroll
            for (int mt = 0; mt < MT; mt++)
                #pragma unroll
                for (int nt = 0; nt < 4; nt++)
                    mma_f16(acc[mt][nt], af[mt], &bf[(nt >> 1) * 4 + (nt & 1) * 2]);
        }
    }
    __syncthreads();

    float*  outf = (float*)outv;
    __half* outh = (__half*)outv;
    const int gid = lane >> 2;
    const int tig = lane & 3;
    #pragma unroll
    for (int nt = 0; nt < 4; nt++) {
        const int n = n0 + wn * 32 + nt * 8 + 2 * tig;
        const float2 bn = *(const float2*)(bias + n);
        #pragma unroll
        for (int mt = 0; mt < MT; mt++) {
            const int r0 = m0 + wm * (MT * 16) + mt * 16 + gid;
            const int r1 = r0 + 8;
            float v0 = acc[mt][nt][0] + bn.x;
            float v1 = acc[mt][nt][1] + bn.y;
            float v2 = acc[mt][nt][2] + bn.x;
            float v3 = acc[mt][nt][3] + bn.y;
            if (EPI == 1) {
                const float2 q0 = *(const float2*)(res + (size_t)r0 * N + n);
                const float2 q1 = *(const float2*)(res + (size_t)r1 * N + n);
                v0 += q0.x; v1 += q0.y; v2 += q1.x; v3 += q1.y;
            }
            if (EPI == 2) {
                v0 = 0.5f * v0 * (1.0f + erff(v0 * 0.70710678118654752f));
                v1 = 0.5f * v1 * (1.0f + erff(v1 * 0.70710678118654752f));
                v2 = 0.5f * v2 * (1.0f + erff(v2 * 0.70710678118654752f));
                v3 = 0.5f * v3 * (1.0f + erff(v3 * 0.70710678118654752f));
            }
            if (OUTH) {
                *(__half2*)(outh + (size_t)r0 * N + n) = __floats2half2_rn(v0, v1);
                *(__half2*)(outh + (size_t)r1 * N + n) = __floats2half2_rn(v2, v3);
            } else {
                *(float2*)(outf + (size_t)r0 * N + n) = make_float2(v0, v1);
                *(float2*)(outf + (size_t)r1 * N + n) = make_float2(v2, v3);
            }
        }
    }
}

// ---------------- LayerNorm (fp32 in, fp16 out: feeds a GEMM only) ----------------
__global__ void ln_kernel(const float* __restrict__ x,
                          const float* __restrict__ w,
                          const float* __restrict__ b,
                          __half* __restrict__ out) {
    int row = blockIdx.x;
    int t = threadIdx.x;
    float v = x[row * CC + t];
    __shared__ float s1[256];
    __shared__ float s2[256];
    s1[t] = v; s2[t] = v * v;
    __syncthreads();
    #pragma unroll
    for (int off = 128; off > 0; off >>= 1) {
        if (t < off) { s1[t] += s1[t + off]; s2[t] += s2[t + off]; }
        __syncthreads();
    }
    float m   = s1[0] * (1.0f / CC);
    float var = s2[0] * (1.0f / CC) - m * m;
    float r   = rsqrtf(var + 1e-5f);
    out[row * CC + t] = __float2half_rn((v - m) * r * w[t] + b[t]);
}

// ---------------- tiled neighborhood attention (fp16 SMEM halo, fp32 compute) ----------------
// 128 blocks (one full wave), 512 threads; block = (16x16 tile, head PAIR, batch).
// Lane pairs (tx, tx+16) split the 32 head channels; one shfl combines scores.
// __launch_bounds__(512, 1): grid is one wave (1 block/SM) — let ptxas use up to
// 128 regs/thread so sc[49]/qf/acc stay in registers (R12's 64-reg clamp spilled).
#define TS    16
#define HALO  22          // TS + 6
#define NHPIX (HALO*HALO) // 484
#define PPH   40          // halfs per halo pixel (32 data + 8 pad); 80B pitch
#define NATT_SMEM (2 * NHPIX * PPH * 2)   // 77440 B (K + V, fp16)

__global__ void __launch_bounds__(512, 1)
natt_tile(const float* __restrict__ qkv, __half* __restrict__ out) {
    extern __shared__ __half hsm[];
    __half* ks = hsm;
    __half* vs = hsm + NHPIX * PPH;

    const int tile  = blockIdx.x;         // 0..15 (4x4 tiles)
    const int hpair = blockIdx.y;         // 0..3
    const int b     = blockIdx.z;
    const int ti0 = (tile >> 2) * TS;
    const int tj0 = (tile & 3) * TS;
    const int tid = threadIdx.x;

    const int lane = tid & 31;
    const int tx   = lane & 15;
    const int half = lane >> 4;           // channel half: 0 or 1
    const int ty   = tid >> 5;            // 0..15
    const int choff = half * 16;          // channel offset within head

    const int hbr = ti0 - 3;
    const int hbc = tj0 - 3;
    const int i = ti0 + ty;
    const int j = tj0 + tx;
    const size_t pix = (size_t)((b * HH + i) * WW + j);

    const int si = min(max(i - 3, 0), HH - KWIN);
    const int sj = min(max(j - 3, 0), WW - KWIN);
    const int lr0 = si - hbr;
    const int lc0 = sj - hbc;

    #pragma unroll
    for (int hp = 0; hp < 2; hp++) {
        const int head  = hpair * 2 + hp;
        const int hbase = head * HDIM;

        // ---- stage K and V halos (fp32 global -> fp16 smem) ----
        for (int idx = tid; idx < NHPIX * 4; idx += 512) {
            const int p  = idx >> 2;
            const int c  = idx & 3;            // 8-channel chunk
            const int hr = p / HALO;
            const int hc = p - hr * HALO;
            const int gr = min(max(hbr + hr, 0), HH - 1);
            const int gc = min(max(hbc + hc, 0), WW - 1);
            const size_t gpix = (size_t)((b * HH + gr) * WW + gc);
            const float* base = qkv + gpix * 768 + hbase + c * 8;
            {
                float4 a = *(const float4*)(base + 256);
                float4 d = *(const float4*)(base + 260);
                uint4 pk;
                pk.x = pack_h2(a.x, a.y); pk.y = pack_h2(a.z, a.w);
                pk.z = pack_h2(d.x, d.y); pk.w = pack_h2(d.z, d.w);
                *(uint4*)(ks + p * PPH + c * 8) = pk;
            }
            {
                float4 a = *(const float4*)(base + 512);
                float4 d = *(const float4*)(base + 516);
                uint4 pv;
                pv.x = pack_h2(a.x, a.y); pv.y = pack_h2(a.z, a.w);
                pv.z = pack_h2(d.x, d.y); pv.w = pack_h2(d.z, d.w);
                *(uint4*)(vs + p * PPH + c * 8) = pv;
            }
        }

        // ---- q (this thread's 16 channels), pre-scaled; overlaps staging ----
        float qf[16];
        {
            const float4* qp = (const float4*)(qkv + pix * 768 + hbase + choff);
            #pragma unroll
            for (int c = 0; c < 4; c++) {
                float4 v = qp[c];
                qf[4*c+0] = v.x * 0.17677669529663687f;
                qf[4*c+1] = v.y * 0.17677669529663687f;
                qf[4*c+2] = v.z * 0.17677669529663687f;
                qf[4*c+3] = v.w * 0.17677669529663687f;
            }
        }
        __syncthreads();

        // ---- QK: 49 half-scores (fp16 K, fp32 accum), combine via 1 shuffle ----
        float sc[49];
        #pragma unroll
        for (int dr = 0; dr < 7; dr++) {
            const __half* rowp = ks + (lr0 + dr) * (HALO * PPH) + lc0 * PPH + choff;
            #pragma unroll
            for (int dc = 0; dc < 7; dc++) {
                const uint4 r0 = *(const uint4*)(rowp + dc * PPH);
                const uint4 r1 = *(const uint4*)(rowp + dc * PPH + 8);
                float2 f0 = unpack_h2(r0.x), f1 = unpack_h2(r0.y);
                float2 f2 = unpack_h2(r0.z), f3 = unpack_h2(r0.w);
                float2 f4 = unpack_h2(r1.x), f5 = unpack_h2(r1.y);
                float2 f6 = unpack_h2(r1.z), f7 = unpack_h2(r1.w);
                float d0 = qf[0] * f0.x + qf[1] * f0.y;
                d0 = fmaf(qf[2],  f1.x, d0); d0 = fmaf(qf[3],  f1.y, d0);
                d0 = fmaf(qf[4],  f2.x, d0); d0 = fmaf(qf[5],  f2.y, d0);
                d0 = fmaf(qf[6],  f3.x, d0); d0 = fmaf(qf[7],  f3.y, d0);
                float d1 = qf[8] * f4.x + qf[9] * f4.y;
                d1 = fmaf(qf[10], f5.x, d1); d1 = fmaf(qf[11], f5.y, d1);
                d1 = fmaf(qf[12], f6.x, d1); d1 = fmaf(qf[13], f6.y, d1);
                d1 = fmaf(qf[14], f7.x, d1); d1 = fmaf(qf[15], f7.y, d1);
                sc[dr * 7 + dc] = d0 + d1;
            }
        }
        #pragma unroll
        for (int n = 0; n < 49; n++)
            sc[n] += __shfl_xor_sync(0xFFFFFFFFu, sc[n], 16);

        // ---- softmax (in-thread; redundant across the lane pair) ----
        float m = sc[0];
        #pragma unroll
        for (int n = 1; n < 49; n++) m = fmaxf(m, sc[n]);
        float den = 0.f;
        #pragma unroll
        for (int n = 0; n < 49; n++) { sc[n] = __expf(sc[n] - m); den += sc[n]; }
        const float inv = 1.0f / den;

        // ---- AV over this thread's 16 channels (fp16 V, fp32 accum) ----
        float acc[16];
        #pragma unroll
        for (int c = 0; c < 16; c++) acc[c] = 0.f;
        #pragma unroll
        for (int dr = 0; dr < 7; dr++) {
            const __half* rowp = vs + (lr0 + dr) * (HALO * PPH) + lc0 * PPH + choff;
            #pragma unroll
            for (int dc = 0; dc < 7; dc++) {
                const float w = sc[dr * 7 + dc];
                const uint4 r0 = *(const uint4*)(rowp + dc * PPH);
                const uint4 r1 = *(const uint4*)(rowp + dc * PPH + 8);
                float2 f0 = unpack_h2(r0.x), f1 = unpack_h2(r0.y);
                float2 f2 = unpack_h2(r0.z), f3 = unpack_h2(r0.w);
                float2 f4 = unpack_h2(r1.x), f5 = unpack_h2(r1.y);
                float2 f6 = unpack_h2(r1.z), f7 = unpack_h2(r1.w);
                acc[0]  = fmaf(w, f0.x, acc[0]);  acc[1]  = fmaf(w, f0.y, acc[1]);
                acc[2]  = fmaf(w, f1.x, acc[2]);  acc[3]  = fmaf(w, f1.y, acc[3]);
                acc[4]  = fmaf(w, f2.x, acc[4]);  acc[5]  = fmaf(w, f2.y, acc[5]);
                acc[6]  = fmaf(w, f3.x, acc[6]);  acc[7]  = fmaf(w, f3.y, acc[7]);
                acc[8]  = fmaf(w, f4.x, acc[8]);  acc[9]  = fmaf(w, f4.y, acc[9]);
                acc[10] = fmaf(w, f5.x, acc[10]); acc[11] = fmaf(w, f5.y, acc[11]);
                acc[12] = fmaf(w, f6.x, acc[12]); acc[13] = fmaf(w, f6.y, acc[13]);
                acc[14] = fmaf(w, f7.x, acc[14]); acc[15] = fmaf(w, f7.y, acc[15]);
            }
        }

        __half2* op = (__half2*)(out + pix * CC + hbase + choff);
        #pragma unroll
        for (int c = 0; c < 8; c++)
            op[c] = __floats2half2_rn(acc[2*c] * inv, acc[2*c+1] * inv);

        if (hp == 0) __syncthreads();   // all reads done before restaging
    }
}

// ---------------- host launcher ----------------
extern "C" void kernel_launch(void* const* d_in, const int* in_sizes, int n_in,
                              void* d_out, int out_size) {
    const float* x      = (const float*)d_in[0];
    const float* ln1_w  = (const float*)d_in[1];
    const float* ln1_b  = (const float*)d_in[2];
    const float* qkv_w  = (const float*)d_in[3];
    const float* qkv_b  = (const float*)d_in[4];
    const float* proj_w = (const float*)d_in[5];
    const float* proj_b = (const float*)d_in[6];
    const float* ln2_w  = (const float*)d_in[7];
    const float* ln2_b  = (const float*)d_in[8];
    const float* fc1_w  = (const float*)d_in[9];
    const float* fc1_b  = (const float*)d_in[10];
    const float* fc2_w  = (const float*)d_in[11];
    const float* fc2_b  = (const float*)d_in[12];
    float* out = (float*)d_out;

    __half *xn, *attn, *hn, *h1, *wh;
    float *qkv;
    cudaGetSymbolAddress((void**)&xn,   g_xn);
    cudaGetSymbolAddress((void**)&qkv,  g_qkv);
    cudaGetSymbolAddress((void**)&attn, g_attn);
    cudaGetSymbolAddress((void**)&hn,   g_hn);
    cudaGetSymbolAddress((void**)&h1,   g_h1);
    cudaGetSymbolAddress((void**)&wh,   g_wh);

    const __half* wh_qkv  = wh;                      // 196608 halfs
    const __half* wh_proj = wh + 196608;             // 65536
    const __half* wh_fc1  = wh + 262144;             // 262144
    const __half* wh_fc2  = wh + 524288;             // 262144

    constexpr int SM128 = 3 * (TILE_A_H + 128 * TPH);  // 61440
    constexpr int SM64  = 3 * (TILE_A_H + 64  * TPH);  // 46080

    cudaFuncSetAttribute((const void*)gemm_tc<0,128,0>, cudaFuncAttributeMaxDynamicSharedMemorySize, SM128);
    cudaFuncSetAttribute((const void*)gemm_tc<2,128,1>, cudaFuncAttributeMaxDynamicSharedMemorySize, SM128);
    cudaFuncSetAttribute((const void*)gemm_tc<1,64,0>,  cudaFuncAttributeMaxDynamicSharedMemorySize, SM64);
    cudaFuncSetAttribute((const void*)natt_tile,        cudaFuncAttributeMaxDynamicSharedMemorySize, NATT_SMEM);

    // 0. convert all weights to fp16 (RN)
    round_weights<<<768, 256>>>((const float4*)qkv_w, (const float4*)proj_w,
                                (const float4*)fc1_w, (const float4*)fc2_w,
                                (__half2*)wh);

    // 1. LN1 -> fp16
    ln_kernel<<<NPIX, 256>>>(x, ln1_w, ln1_b, xn);

    // 2. QKV GEMM: [8192,256] x [768,256]^T -> fp32 (attention reads fp32)
    gemm_tc<0,128,0><<<dim3(768 / 128, NPIX / 128), 256, SM128>>>(
        xn, wh_qkv, qkv_b, nullptr, qkv, NPIX, 768, CC);

    // 3. tiled neighborhood attention (fp16 halo) -> fp16
    natt_tile<<<dim3(16, NHE / 2, BB), 512, NATT_SMEM>>>(qkv, attn);

    // 4. proj GEMM + bias + residual(x) -> fp32 d_out   (BN=64: 256 blocks)
    gemm_tc<1,64,0><<<dim3(CC / 64, NPIX / 128), 256, SM64>>>(
        attn, wh_proj, proj_b, x, out, NPIX, CC, CC);

    // 5. LN2 -> fp16
    ln_kernel<<<NPIX, 256>>>(out, ln2_w, ln2_b, hn);

    // 6. fc1 GEMM + exact GELU -> fp16
    gemm_tc<2,128,1><<<dim3(1024 / 128, NPIX / 128), 256, SM128>>>(
        hn, wh_fc1, fc1_b, nullptr, h1, NPIX, 1024, CC);

    // 7. fc2 GEMM + bias + residual(d_out) -> fp32 d_out   (BN=64: 256 blocks)
    gemm_tc<1,64,0><<<dim3(CC / 64, NPIX / 128), 256, SM64>>>(
        h1, wh_fc2, fc2_b, out, out, NPIX, CC, 1024);
}

// round 14
// speedup vs baseline: 1.1331x; 1.0800x over previous
#include <cuda_runtime.h>
#include <cuda_fp16.h>
#include <cstdint>
#include <math.h>

#define BB   2
#define HH   64
#define WW   64
#define CC   256
#define NHE  8
#define HDIM 32
#define KWIN 7
#define NPIX (BB*HH*WW)   // 8192

// ---------------- scratch (no allocation allowed) ----------------
__device__ __align__(16) __half g_xn  [NPIX * CC];
__device__ float               g_qkv [NPIX * 3 * CC];
__device__ __align__(16) __half g_attn[NPIX * CC];
__device__ __align__(16) __half g_hn  [NPIX * CC];
__device__ __align__(16) __half g_h1  [NPIX * 4 * CC];
__device__ __align__(16) __half g_wh  [12 * CC * CC];   // fp16 weights: qkv|proj|fc1|fc2

// ======================= PTX helpers (sm_80-era only; target is plain sm_103) ===============
__device__ __forceinline__ uint32_t smem_u32(const void* p) {
    uint32_t a;
    asm("{ .reg .u64 t; cvta.to.shared.u64 t, %1; cvt.u32.u64 %0, t; }" : "=r"(a) : "l"(p));
    return a;
}

#define CP_ASYNC16(dst, src) \
    asm volatile("cp.async.cg.shared.global [%0], [%1], 16;" :: "r"(dst), "l"(src) : "memory")
#define CP_COMMIT()  asm volatile("cp.async.commit_group;" ::: "memory")
#define CP_WAIT(n)   asm volatile("cp.async.wait_group %0;" :: "n"(n) : "memory")

__device__ __forceinline__ void ldsm_x4(uint32_t* r, uint32_t addr) {
    asm volatile("ldmatrix.sync.aligned.m8n8.x4.shared.b16 {%0,%1,%2,%3}, [%4];"
                 : "=r"(r[0]), "=r"(r[1]), "=r"(r[2]), "=r"(r[3]) : "r"(addr));
}

__device__ __forceinline__ void mma_f16(float* c, const uint32_t* a, const uint32_t* b) {
    asm volatile("mma.sync.aligned.m16n8k16.row.col.f32.f16.f16.f32 "
                 "{%0,%1,%2,%3}, {%4,%5,%6,%7}, {%8,%9}, {%0,%1,%2,%3};"
                 : "+f"(c[0]), "+f"(c[1]), "+f"(c[2]), "+f"(c[3])
                 : "r"(a[0]), "r"(a[1]), "r"(a[2]), "r"(a[3]), "r"(b[0]), "r"(b[1]));
}

__device__ __forceinline__ uint32_t pack_h2(float x, float y) {
    __half2 h = __floats2half2_rn(x, y);
    return *(uint32_t*)&h;
}

__device__ __forceinline__ float2 unpack_h2(uint32_t u) {
    return __half22float2(*(const __half2*)&u);
}

// fp16 SMEM tile: rows x 32 halfs (64B data), padded to 80B pitch.
#define TPH      80
#define TILE_A_H (128 * TPH)                          // 10240 B

// ---------------- convert weights to fp16 (RN) ----------------
// concatenated float4 ranges: qkv 49152 | proj 16384 | fc1 65536 | fc2 65536
__global__ void round_weights(const float4* __restrict__ w0,
                              const float4* __restrict__ w1,
                              const float4* __restrict__ w2,
                              const float4* __restrict__ w3,
                              __half2* __restrict__ out) {
    int i = blockIdx.x * 256 + threadIdx.x;     // 0 .. 196607
    const float4* src;
    int off;
    if      (i <  49152) { src = w0; off = 0;      }
    else if (i <  65536) { src = w1; off = 49152;  }
    else if (i < 131072) { src = w2; off = 65536;  }
    else                 { src = w3; off = 131072; }
    float4 v = src[i - off];
    out[2 * i]     = __floats2half2_rn(v.x, v.y);
    out[2 * i + 1] = __floats2half2_rn(v.z, v.w);
}

// ============ fp16 m16n8k16 GEMM, 3-stage pipeline ============
// out[M,N] = A[M,K] * W[N,K]^T + bias (+res/+gelu).  Tile: 128 x BN (BN in {128, 64}).
// EPI: 0 = bias, 1 = bias + residual, 2 = bias + exact GELU
// OUTH: 0 = fp32 output, 1 = fp16 output
template <int EPI, int BN, int OUTH>
__global__ void __launch_bounds__(256, 2)
gemm_tc(const __half* __restrict__ A,
        const __half* __restrict__ Wm,
        const float* __restrict__ bias,
        const float* __restrict__ res,
        void* __restrict__ outv,
        int M, int N, int Kd) {
    constexpr int WN    = BN / 32;        // warps along N
    constexpr int WM    = 8 / WN;         // warps along M
    constexpr int MT    = 128 / (16 * WM);// m16 tiles per warp
    constexpr int STAGE = TILE_A_H + BN * TPH;

    extern __shared__ __align__(1024) char smem[];
    const uint32_t sb = smem_u32(smem);

    const int tid  = threadIdx.x;
    const int wid  = tid >> 5;
    const int lane = tid & 31;
    const int wm   = wid / WN;
    const int wn   = wid % WN;
    const int m0   = blockIdx.y * 128;
    const int n0   = blockIdx.x * BN;
    const int niters = Kd >> 5;           // K slabs of 32 halfs (64B)

    const int sub = lane >> 3;
    const int mr  = lane & 7;
    const uint32_t aoff = (uint32_t)((wm * (MT * 16) + (sub & 1) * 8 + mr) * TPH + (sub >> 1) * 16);
    const uint32_t boff = (uint32_t)(TILE_A_H + (wn * 32 + (sub >> 1) * 8 + mr) * TPH + (sub & 1) * 16);

    float acc[MT][4][4];
    #pragma unroll
    for (int i = 0; i < MT; i++)
        #pragma unroll
        for (int j = 0; j < 4; j++)
            #pragma unroll
            for (int k = 0; k < 4; k++) acc[i][j][k] = 0.0f;

    auto load_stage = [&](int it, int s) {
        const uint32_t base = sb + s * STAGE;
        #pragma unroll
        for (int idx = 0; idx < 2; idx++) {
            const int t = tid + idx * 256;        // 0..511 (128 rows x 4 chunks)
            const int row = t >> 2, c = t & 3;
            CP_ASYNC16(base + row * TPH + c * 16,
                       A + (size_t)(m0 + row) * Kd + it * 32 + c * 8);
        }
        #pragma unroll
        for (int idx = 0; idx < BN / 64; idx++) {
            const int t = tid + idx * 256;        // 0..BN*4-1
            const int row = t >> 2, c = t & 3;
            CP_ASYNC16(base + TILE_A_H + row * TPH + c * 16,
                       Wm + (size_t)(n0 + row) * Kd + it * 32 + c * 8);
        }
    };

    load_stage(0, 0); CP_COMMIT();
    load_stage(1, 1); CP_COMMIT();

    for (int it = 0; it < niters; it++) {
        const int s = it - (it / 3) * 3;
        CP_WAIT(1);                 // stage `it` resident
        __syncthreads();
        const int p = it + 2;
        if (p < niters) load_stage(p, p - (p / 3) * 3);
        CP_COMMIT();

        const uint32_t Ab = sb + s * STAGE;

        #pragma unroll
        for (int ks = 0; ks < 2; ks++) {          // two k16 steps per 32-half slab
            uint32_t af[MT][4];
            #pragma unroll
            for (int mt = 0; mt < MT; mt++)
                ldsm_x4(af[mt], Ab + aoff + mt * (16 * TPH) + ks * 32);
            uint32_t bf[8];
            #pragma unroll
            for (int pp = 0; pp < 2; pp++)
                ldsm_x4(&bf[pp * 4], Ab + boff + pp * (16 * TPH) + ks * 32);
            #pragma unroll
            for (int mt = 0; mt < MT; mt++)
                #pragma unroll
                for (int nt = 0; nt < 4; nt++)
                    mma_f16(acc[mt][nt], af[mt], &bf[(nt >> 1) * 4 + (nt & 1) * 2]);
        }
    }
    __syncthreads();

    float*  outf = (float*)outv;
    __half* outh = (__half*)outv;
    const int gid = lane >> 2;
    const int tig = lane & 3;
    #pragma unroll
    for (int nt = 0; nt < 4; nt++) {
        const int n = n0 + wn * 32 + nt * 8 + 2 * tig;
        const float2 bn = *(const float2*)(bias + n);
        #pragma unroll
        for (int mt = 0; mt < MT; mt++) {
            const int r0 = m0 + wm * (MT * 16) + mt * 16 + gid;
            const int r1 = r0 + 8;
            float v0 = acc[mt][nt][0] + bn.x;
            float v1 = acc[mt][nt][1] + bn.y;
            float v2 = acc[mt][nt][2] + bn.x;
            float v3 = acc[mt][nt][3] + bn.y;
            if (EPI == 1) {
                const float2 q0 = *(const float2*)(res + (size_t)r0 * N + n);
                const float2 q1 = *(const float2*)(res + (size_t)r1 * N + n);
                v0 += q0.x; v1 += q0.y; v2 += q1.x; v3 += q1.y;
            }
            if (EPI == 2) {
                v0 = 0.5f * v0 * (1.0f + erff(v0 * 0.70710678118654752f));
                v1 = 0.5f * v1 * (1.0f + erff(v1 * 0.70710678118654752f));
                v2 = 0.5f * v2 * (1.0f + erff(v2 * 0.70710678118654752f));
                v3 = 0.5f * v3 * (1.0f + erff(v3 * 0.70710678118654752f));
            }
            if (OUTH) {
                *(__half2*)(outh + (size_t)r0 * N + n) = __floats2half2_rn(v0, v1);
                *(__half2*)(outh + (size_t)r1 * N + n) = __floats2half2_rn(v2, v3);
            } else {
                *(float2*)(outf + (size_t)r0 * N + n) = make_float2(v0, v1);
                *(float2*)(outf + (size_t)r1 * N + n) = make_float2(v2, v3);
            }
        }
    }
}

// ---------------- LayerNorm (fp32 in, fp16 out: feeds a GEMM only) ----------------
__global__ void ln_kernel(const float* __restrict__ x,
                          const float* __restrict__ w,
                          const float* __restrict__ b,
                          __half* __restrict__ out) {
    int row = blockIdx.x;
    int t = threadIdx.x;
    float v = x[row * CC + t];
    __shared__ float s1[256];
    __shared__ float s2[256];
    s1[t] = v; s2[t] = v * v;
    __syncthreads();
    #pragma unroll
    for (int off = 128; off > 0; off >>= 1) {
        if (t < off) { s1[t] += s1[t + off]; s2[t] += s2[t + off]; }
        __syncthreads();
    }
    float m   = s1[0] * (1.0f / CC);
    float var = s2[0] * (1.0f / CC) - m * m;
    float r   = rsqrtf(var + 1e-5f);
    out[row * CC + t] = __float2half_rn((v - m) * r * w[t] + b[t]);
}

// ---------------- tiled neighborhood attention ----------------
// 128 blocks (one full wave), 512 threads; block = (16x16 tile, head PAIR, batch).
// K halo in fp16 (halved QK crossbar bytes), V halo in fp32 (R10's proven AV path).
// Lane pairs (tx, tx+16) split the 32 head channels; one shfl combines scores.
#define TS    16
#define HALO  22          // TS + 6
#define NHPIX (HALO*HALO) // 484
#define PPH   40          // halfs per K halo pixel (32 data + 8 pad); 80B pitch
#define PPITCH 36         // floats per V halo pixel (32 data + 4 pad); 144B pitch
#define KS_BYTES (NHPIX * PPH * 2)        // 38720
#define NATT_SMEM (KS_BYTES + NHPIX * PPITCH * 4)   // 108416 B -> 1 block/SM

__global__ void __launch_bounds__(512, 1)
natt_tile(const float* __restrict__ qkv, __half* __restrict__ out) {
    extern __shared__ __align__(16) char nsm[];
    __half* ks = (__half*)nsm;
    float*  vs = (float*)(nsm + KS_BYTES);

    const int tile  = blockIdx.x;         // 0..15 (4x4 tiles)
    const int hpair = blockIdx.y;         // 0..3
    const int b     = blockIdx.z;
    const int ti0 = (tile >> 2) * TS;
    const int tj0 = (tile & 3) * TS;
    const int tid = threadIdx.x;

    const int lane = tid & 31;
    const int tx   = lane & 15;
    const int half = lane >> 4;           // channel half: 0 or 1
    const int ty   = tid >> 5;            // 0..15
    const int choff = half * 16;          // channel offset within head

    const int hbr = ti0 - 3;
    const int hbc = tj0 - 3;
    const int i = ti0 + ty;
    const int j = tj0 + tx;
    const size_t pix = (size_t)((b * HH + i) * WW + j);

    const int si = min(max(i - 3, 0), HH - KWIN);
    const int sj = min(max(j - 3, 0), WW - KWIN);
    const int lr0 = si - hbr;
    const int lc0 = sj - hbc;

    #pragma unroll
    for (int hp = 0; hp < 2; hp++) {
        const int head  = hpair * 2 + hp;
        const int hbase = head * HDIM;

        // ---- stage V halo (fp32, as in R10) ----
        for (int idx = tid; idx < NHPIX * 8; idx += 512) {
            const int p  = idx >> 3;
            const int c  = idx & 7;
            const int hr = p / HALO;
            const int hc = p - hr * HALO;
            const int gr = min(max(hbr + hr, 0), HH - 1);
            const int gc = min(max(hbc + hc, 0), WW - 1);
            const size_t gpix = (size_t)((b * HH + gr) * WW + gc);
            *(float4*)(vs + p * PPITCH + c * 4) =
                *(const float4*)(qkv + gpix * 768 + hbase + 512 + c * 4);
        }
        // ---- stage K halo (fp32 global -> fp16 smem) ----
        for (int idx = tid; idx < NHPIX * 4; idx += 512) {
            const int p  = idx >> 2;
            const int c  = idx & 3;            // 8-channel chunk
            const int hr = p / HALO;
            const int hc = p - hr * HALO;
            const int gr = min(max(hbr + hr, 0), HH - 1);
            const int gc = min(max(hbc + hc, 0), WW - 1);
            const size_t gpix = (size_t)((b * HH + gr) * WW + gc);
            const float* base = qkv + gpix * 768 + hbase + 256 + c * 8;
            float4 a = *(const float4*)(base);
            float4 d = *(const float4*)(base + 4);
            uint4 pk;
            pk.x = pack_h2(a.x, a.y); pk.y = pack_h2(a.z, a.w);
            pk.z = pack_h2(d.x, d.y); pk.w = pack_h2(d.z, d.w);
            *(uint4*)(ks + p * PPH + c * 8) = pk;
        }

        // ---- q (this thread's 16 channels), pre-scaled; overlaps staging ----
        float qf[16];
        {
            const float4* qp = (const float4*)(qkv + pix * 768 + hbase + choff);
            #pragma unroll
            for (int c = 0; c < 4; c++) {
                float4 v = qp[c];
                qf[4*c+0] = v.x * 0.17677669529663687f;
                qf[4*c+1] = v.y * 0.17677669529663687f;
                qf[4*c+2] = v.z * 0.17677669529663687f;
                qf[4*c+3] = v.w * 0.17677669529663687f;
            }
        }
        __syncthreads();

        // ---- QK: fp16 K, fp32 accum; combine lane pair via 1 shuffle ----
        float sc[49];
        #pragma unroll
        for (int dr = 0; dr < 7; dr++) {
            const __half* rowp = ks + (lr0 + dr) * (HALO * PPH) + lc0 * PPH + choff;
            #pragma unroll
            for (int dc = 0; dc < 7; dc++) {
                const uint4 r0 = *(const uint4*)(rowp + dc * PPH);
                const uint4 r1 = *(const uint4*)(rowp + dc * PPH + 8);
                float2 f0 = unpack_h2(r0.x), f1 = unpack_h2(r0.y);
                float2 f2 = unpack_h2(r0.z), f3 = unpack_h2(r0.w);
                float2 f4 = unpack_h2(r1.x), f5 = unpack_h2(r1.y);
                float2 f6 = unpack_h2(r1.z), f7 = unpack_h2(r1.w);
                float d0 = qf[0] * f0.x + qf[1] * f0.y;
                d0 = fmaf(qf[2],  f1.x, d0); d0 = fmaf(qf[3],  f1.y, d0);
                d0 = fmaf(qf[4],  f2.x, d0); d0 = fmaf(qf[5],  f2.y, d0);
                d0 = fmaf(qf[6],  f3.x, d0); d0 = fmaf(qf[7],  f3.y, d0);
                float d1 = qf[8] * f4.x + qf[9] * f4.y;
                d1 = fmaf(qf[10], f5.x, d1); d1 = fmaf(qf[11], f5.y, d1);
                d1 = fmaf(qf[12], f6.x, d1); d1 = fmaf(qf[13], f6.y, d1);
                d1 = fmaf(qf[14], f7.x, d1); d1 = fmaf(qf[15], f7.y, d1);
                sc[dr * 7 + dc] = d0 + d1;
            }
        }
        #pragma unroll
        for (int n = 0; n < 49; n++)
            sc[n] += __shfl_xor_sync(0xFFFFFFFFu, sc[n], 16);

        // ---- softmax (in-thread; redundant across the lane pair) ----
        float m = sc[0];
        #pragma unroll
        for (int n = 1; n < 49; n++) m = fmaxf(m, sc[n]);
        float den = 0.f;
        #pragma unroll
        for (int n = 0; n < 49; n++) { sc[n] = __expf(sc[n] - m); den += sc[n]; }
        const float inv = 1.0f / den;

        // ---- AV over this thread's 16 channels (fp32 V, exactly R10) ----
        float4 acc[4];
        #pragma unroll
        for (int c = 0; c < 4; c++) acc[c] = make_float4(0.f, 0.f, 0.f, 0.f);
        #pragma unroll
        for (int dr = 0; dr < 7; dr++) {
            const float* rowp = vs + (lr0 + dr) * (HALO * PPITCH) + lc0 * PPITCH + choff;
            #pragma unroll
            for (int dc = 0; dc < 7; dc++) {
                const float w = sc[dr * 7 + dc];
                const float* vp = rowp + dc * PPITCH;
                #pragma unroll
                for (int c = 0; c < 4; c++) {
                    float4 vv = *(const float4*)(vp + c * 4);
                    acc[c].x = fmaf(w, vv.x, acc[c].x);
                    acc[c].y = fmaf(w, vv.y, acc[c].y);
                    acc[c].z = fmaf(w, vv.z, acc[c].z);
                    acc[c].w = fmaf(w, vv.w, acc[c].w);
                }
            }
        }

        __half2* op = (__half2*)(out + pix * CC + hbase + choff);
        #pragma unroll
        for (int c = 0; c < 4; c++) {
            op[2 * c]     = __floats2half2_rn(acc[c].x * inv, acc[c].y * inv);
            op[2 * c + 1] = __floats2half2_rn(acc[c].z * inv, acc[c].w * inv);
        }
        if (hp == 0) __syncthreads();   // all reads done before restaging
    }
}

// ---------------- host launcher ----------------
extern "C" void kernel_launch(void* const* d_in, const int* in_sizes, int n_in,
                              void* d_out, int out_size) {
    const float* x      = (const float*)d_in[0];
    const float* ln1_w  = (const float*)d_in[1];
    const float* ln1_b  = (const float*)d_in[2];
    const float* qkv_w  = (const float*)d_in[3];
    const float* qkv_b  = (const float*)d_in[4];
    const float* proj_w = (const float*)d_in[5];
    const float* proj_b = (const float*)d_in[6];
    const float* ln2_w  = (const float*)d_in[7];
    const float* ln2_b  = (const float*)d_in[8];
    const float* fc1_w  = (const float*)d_in[9];
    const float* fc1_b  = (const float*)d_in[10];
    const float* fc2_w  = (const float*)d_in[11];
    const float* fc2_b  = (const float*)d_in[12];
    float* out = (float*)d_out;

    __half *xn, *attn, *hn, *h1, *wh;
    float *qkv;
    cudaGetSymbolAddress((void**)&xn,   g_xn);
    cudaGetSymbolAddress((void**)&qkv,  g_qkv);
    cudaGetSymbolAddress((void**)&attn, g_attn);
    cudaGetSymbolAddress((void**)&hn,   g_hn);
    cudaGetSymbolAddress((void**)&h1,   g_h1);
    cudaGetSymbolAddress((void**)&wh,   g_wh);

    const __half* wh_qkv  = wh;                      // 196608 halfs
    const __half* wh_proj = wh + 196608;             // 65536
    const __half* wh_fc1  = wh + 262144;             // 262144
    const __half* wh_fc2  = wh + 524288;             // 262144

    constexpr int SM128 = 3 * (TILE_A_H + 128 * TPH);  // 61440
    constexpr int SM64  = 3 * (TILE_A_H + 64  * TPH);  // 46080

    cudaFuncSetAttribute((const void*)gemm_tc<0,128,0>, cudaFuncAttributeMaxDynamicSharedMemorySize, SM128);
    cudaFuncSetAttribute((const void*)gemm_tc<2,128,1>, cudaFuncAttributeMaxDynamicSharedMemorySize, SM128);
    cudaFuncSetAttribute((const void*)gemm_tc<1,64,0>,  cudaFuncAttributeMaxDynamicSharedMemorySize, SM64);
    cudaFuncSetAttribute((const void*)natt_tile,        cudaFuncAttributeMaxDynamicSharedMemorySize, NATT_SMEM);

    // 0. convert all weights to fp16 (RN)
    round_weights<<<768, 256>>>((const float4*)qkv_w, (const float4*)proj_w,
                                (const float4*)fc1_w, (const float4*)fc2_w,
                                (__half2*)wh);

    // 1. LN1 -> fp16
    ln_kernel<<<NPIX, 256>>>(x, ln1_w, ln1_b, xn);

    // 2. QKV GEMM: [8192,256] x [768,256]^T -> fp32 (attention reads fp32)
    gemm_tc<0,128,0><<<dim3(768 / 128, NPIX / 128), 256, SM128>>>(
        xn, wh_qkv, qkv_b, nullptr, qkv, NPIX, 768, CC);

    // 3. tiled neighborhood attention (fp16 K halo, fp32 V halo) -> fp16
    natt_tile<<<dim3(16, NHE / 2, BB), 512, NATT_SMEM>>>(qkv, attn);

    // 4. proj GEMM + bias + residual(x) -> fp32 d_out   (BN=64: 256 blocks)
    gemm_tc<1,64,0><<<dim3(CC / 64, NPIX / 128), 256, SM64>>>(
        attn, wh_proj, proj_b, x, out, NPIX, CC, CC);

    // 5. LN2 -> fp16
    ln_kernel<<<NPIX, 256>>>(out, ln2_w, ln2_b, hn);

    // 6. fc1 GEMM + exact GELU -> fp16
    gemm_tc<2,128,1><<<dim3(1024 / 128, NPIX / 128), 256, SM128>>>(
        hn, wh_fc1, fc1_b, nullptr, h1, NPIX, 1024, CC);

    // 7. fc2 GEMM + bias + residual(d_out) -> fp32 d_out   (BN=64: 256 blocks)
    gemm_tc<1,64,0><<<dim3(CC / 64, NPIX / 128), 256, SM64>>>(
        h1, wh_fc2, fc2_b, out, out, NPIX, CC, 1024);
}